// round 4
// baseline (speedup 1.0000x reference)
#include <cuda_runtime.h>
#include <cuda_fp16.h>

#define BB 8
#define NN 5000
#define EE 100000
#define DD 128
#define NB (BB * NN)        // 40000
#define NE (BB * EE)        // 800000

typedef unsigned long long u64;
typedef unsigned int u32;

// Scratch (allocation-free: __device__ globals)
__device__ __align__(16) int   g_deg[NB];
__device__ __align__(16) int   g_off[NB];
__device__ __align__(16) int   g_cursor[NB];
__device__ __align__(16) int2  g_bin[NE];
__device__ __align__(16) float g_mean[NB * DD];
__device__ __align__(16) uint2 g_xh[NB * DD / 4];   // x as half2 pairs (10.2MB)

// ---------------------------------------------------------------------------
// K0: zero degree counters + convert x -> fp16 (independent work, one kernel)
// ---------------------------------------------------------------------------
__global__ void prep_kernel(const float* __restrict__ x) {
    int i = blockIdx.x * blockDim.x + threadIdx.x;
    if (i < NB) g_deg[i] = 0;
    if (i < NB * DD / 4) {
        float4 v = __ldg(&((const float4*)x)[i]);
        __half2 h0 = __floats2half2_rn(v.x, v.y);
        __half2 h1 = __floats2half2_rn(v.z, v.w);
        g_xh[i] = make_uint2(*(u32*)&h0, *(u32*)&h1);
    }
}

// ---------------------------------------------------------------------------
// K1: histogram of edge targets. 4 edges/thread, int4 load, RED (no return).
// EE % 4 == 0 so a 4-batch never crosses a batch boundary.
// ---------------------------------------------------------------------------
__global__ void hist_kernel(const int* __restrict__ ei) {
    int t = blockIdx.x * blockDim.x + threadIdx.x;
    int base = t * 4;
    if (base >= NE) return;
    int b = base / EE;
    int e = base - b * EE;
    int4 t4 = __ldg((const int4*)&ei[(size_t)b * 2 * EE + EE + e]);
    int* deg = g_deg + b * NN;
    atomicAdd(&deg[t4.x], 1);
    atomicAdd(&deg[t4.y], 1);
    atomicAdd(&deg[t4.z], 1);
    atomicAdd(&deg[t4.w], 1);
}

// ---------------------------------------------------------------------------
// K2: exclusive prefix sum over 40000 degrees (single block, vectorized)
// ---------------------------------------------------------------------------
__global__ void __launch_bounds__(1024, 1) scan_kernel() {
    __shared__ int part[1024];
    const int t = threadIdx.x;
    const int CH = 40;
    int lo = t * CH;
    if (lo < NB) {
        const int4* d4 = (const int4*)(g_deg + lo);
        int s = 0;
#pragma unroll
        for (int i = 0; i < CH / 4; ++i) {
            int4 v = d4[i];
            s += v.x + v.y + v.z + v.w;
        }
        part[t] = s;
    } else {
        part[t] = 0;
    }
    __syncthreads();

    for (int o = 1; o < 1024; o <<= 1) {
        int v = (t >= o) ? part[t - o] : 0;
        __syncthreads();
        part[t] += v;
        __syncthreads();
    }

    if (lo < NB) {
        int run = (t > 0) ? part[t - 1] : 0;
        const int4* d4 = (const int4*)(g_deg + lo);
        int4* o4 = (int4*)(g_off + lo);
        int4* c4 = (int4*)(g_cursor + lo);
#pragma unroll
        for (int i = 0; i < CH / 4; ++i) {
            int4 v = d4[i];
            int4 w;
            w.x = run; run += v.x;
            w.y = run; run += v.y;
            w.z = run; run += v.z;
            w.w = run; run += v.w;
            o4[i] = w;
            c4[i] = w;
        }
    }
}

// ---------------------------------------------------------------------------
// K3: fill bins. 4 edges/thread, vector loads, 4 independent atomic chains.
// ---------------------------------------------------------------------------
__global__ void fill_kernel(const int* __restrict__ ei,
                            const float* __restrict__ em) {
    int t = blockIdx.x * blockDim.x + threadIdx.x;
    int base = t * 4;
    if (base >= NE) return;
    int b = base / EE;
    int e = base - b * EE;
    const int* eb = ei + (size_t)b * 2 * EE;
    int4 s4 = __ldg((const int4*)&eb[e]);
    int4 t4 = __ldg((const int4*)&eb[EE + e]);
    float4 m4 = __ldg((const float4*)&em[(size_t)b * EE + e]);
    int* cur = g_cursor + b * NN;
    int p0 = atomicAdd(&cur[t4.x], 1);
    int p1 = atomicAdd(&cur[t4.y], 1);
    int p2 = atomicAdd(&cur[t4.z], 1);
    int p3 = atomicAdd(&cur[t4.w], 1);
    g_bin[p0] = make_int2(s4.x, __float_as_int(m4.x));
    g_bin[p1] = make_int2(s4.y, __float_as_int(m4.y));
    g_bin[p2] = make_int2(s4.z, __float_as_int(m4.z));
    g_bin[p3] = make_int2(s4.w, __float_as_int(m4.w));
}

// ---------------------------------------------------------------------------
// K4: gather (fp16 rows). One warp per target node; lane owns cols 4L..4L+3
// (uint2 = 4 halfs = 8B/lane -> 256B/row). 4-edge unroll for MLP.
// ---------------------------------------------------------------------------
__global__ void gather_kernel() {
    int g = (blockIdx.x * blockDim.x + threadIdx.x) >> 5;
    int lane = threadIdx.x & 31;
    if (g >= NB) return;
    int b = g / NN;

    const int deg = g_deg[g];
    const int off = g_off[g];
    const uint2* xr = g_xh + (size_t)b * NN * 32;

    float4 acc = make_float4(0.f, 0.f, 0.f, 0.f);
    float cm = 0.f;

#define EDGE_FMA(u, m)                                                        \
    {                                                                         \
        float2 a = __half22float2(*(__half2*)&(u).x);                         \
        float2 c = __half22float2(*(__half2*)&(u).y);                         \
        acc.x = fmaf(a.x, (m), acc.x);                                        \
        acc.y = fmaf(a.y, (m), acc.y);                                        \
        acc.z = fmaf(c.x, (m), acc.z);                                        \
        acc.w = fmaf(c.y, (m), acc.w);                                        \
        cm += (m);                                                            \
    }

    int j = 0;
    for (; j + 4 <= deg; j += 4) {
        int2 r0 = __ldg(&g_bin[off + j]);
        int2 r1 = __ldg(&g_bin[off + j + 1]);
        int2 r2 = __ldg(&g_bin[off + j + 2]);
        int2 r3 = __ldg(&g_bin[off + j + 3]);
        uint2 u0 = __ldg(&xr[(size_t)r0.x * 32 + lane]);
        uint2 u1 = __ldg(&xr[(size_t)r1.x * 32 + lane]);
        uint2 u2 = __ldg(&xr[(size_t)r2.x * 32 + lane]);
        uint2 u3 = __ldg(&xr[(size_t)r3.x * 32 + lane]);
        EDGE_FMA(u0, __int_as_float(r0.y))
        EDGE_FMA(u1, __int_as_float(r1.y))
        EDGE_FMA(u2, __int_as_float(r2.y))
        EDGE_FMA(u3, __int_as_float(r3.y))
    }
    for (; j < deg; ++j) {
        int2 r = __ldg(&g_bin[off + j]);
        uint2 u = __ldg(&xr[(size_t)r.x * 32 + lane]);
        EDGE_FMA(u, __int_as_float(r.y))
    }
#undef EDGE_FMA

    float inv = 1.f / fmaxf(cm, 1.f);
    float4 o;
    o.x = acc.x * inv; o.y = acc.y * inv; o.z = acc.z * inv; o.w = acc.w * inv;
    ((float4*)g_mean)[(size_t)g * 32 + lane] = o;
}

// ---------------------------------------------------------------------------
// K5: fused GEMM (fma.rn.f32x2) + relu + LN + mask.
// 256 threads, 8 warps; warp owns 8 nodes; lane cg owns cols cg+32J.
// 8 nodes/thread halves weight-LDS traffic per FMA vs round 3:
// crossbar demand ~136 B/cyc vs 128 capacity -> near FMA-issue bound.
// ---------------------------------------------------------------------------
#define TILE_NODES 64
#define FUSED_THREADS 256
#define W_PITCH 260
#define WCT_FLOATS (128 * W_PITCH)
#define INS_FLOATS (TILE_NODES * 256)
#define FUSED_SMEM_BYTES ((WCT_FLOATS + INS_FLOATS) * 4)
#define W_COLSTRIDE (32 * W_PITCH / 4)   // ulonglong2 stride between col groups

__device__ __forceinline__ void fma2(u64& d, u64 a, u64 b) {
    asm("fma.rn.f32x2 %0, %1, %2, %0;" : "+l"(d) : "l"(a), "l"(b));
}
__device__ __forceinline__ float2 unpack2(u64 v) {
    float2 u;
    asm("mov.b64 {%0, %1}, %2;" : "=f"(u.x), "=f"(u.y) : "l"(v));
    return u;
}

__global__ void __launch_bounds__(FUSED_THREADS, 1)
fused_kernel(const float* __restrict__ x,
             const float* __restrict__ Wself,
             const float* __restrict__ bself,
             const float* __restrict__ Wnb,
             const float* __restrict__ bnb,
             const float* __restrict__ gamma,
             const float* __restrict__ beta,
             const float* __restrict__ nmask,
             float* __restrict__ out) {
    extern __shared__ float smemf[];
    float* WcT = smemf;                 // [128 cols][260] transposed weights
    float* inS = smemf + WCT_FLOATS;    // [64 nodes][256 k]

    const int tid = threadIdx.x;
    const int cg = tid & 31;   // base column; thread owns cols cg+32J
    const int ng = tid >> 5;   // warp -> nodes ng*8 .. ng*8+7

    // Load concatenated transposed weights (coalesced gmem, strided smem)
    for (int i = tid; i < 256 * 128; i += FUSED_THREADS) {
        int k = i >> 7;
        int col = i & 127;
        float w = (k < 128) ? __ldg(&Wself[k * 128 + col])
                            : __ldg(&Wnb[(k - 128) * 128 + col]);
        WcT[col * W_PITCH + k] = w;
    }
    __syncthreads();

    float bias[4], gm[4], bt[4];
#pragma unroll
    for (int J = 0; J < 4; ++J) {
        int c = cg + 32 * J;
        bias[J] = __ldg(&bself[c]) + __ldg(&bnb[c]);
        gm[J] = __ldg(&gamma[c]);
        bt[J] = __ldg(&beta[c]);
    }

    const int ntiles = NB / TILE_NODES;  // 625
    const float4* x4 = (const float4*)x;
    const float4* m4 = (const float4*)g_mean;

    const ulonglong2* wBase = (const ulonglong2*)(WcT + cg * W_PITCH);
    const ulonglong2* aBase = (const ulonglong2*)(inS + ng * 8 * 256);

    for (int tile = blockIdx.x; tile < ntiles; tile += gridDim.x) {
        const int node0 = tile * TILE_NODES;

        // inS[nl][k]: k<128 -> x row, k>=128 -> mean row
        for (int i = tid; i < TILE_NODES * 64; i += FUSED_THREADS) {
            int nl = i >> 6;
            int k4 = i & 63;
            int gn = node0 + nl;
            float4 v = (k4 < 32) ? x4[(size_t)gn * 32 + k4]
                                 : m4[(size_t)gn * 32 + (k4 - 32)];
            ((float4*)inS)[(size_t)nl * 64 + k4] = v;
        }
        __syncthreads();

        u64 acc[8][4];
#pragma unroll
        for (int n = 0; n < 8; ++n)
#pragma unroll
            for (int J = 0; J < 4; ++J)
                acc[n][J] = 0ull;

#pragma unroll 2
        for (int k4 = 0; k4 < 64; ++k4) {
            ulonglong2 w0 = wBase[k4];
            ulonglong2 w1 = wBase[k4 + W_COLSTRIDE];
            ulonglong2 w2 = wBase[k4 + 2 * W_COLSTRIDE];
            ulonglong2 w3 = wBase[k4 + 3 * W_COLSTRIDE];
#pragma unroll
            for (int n = 0; n < 8; ++n) {
                ulonglong2 a = aBase[k4 + n * 64];
                fma2(acc[n][0], a.x, w0.x);
                fma2(acc[n][0], a.y, w0.y);
                fma2(acc[n][1], a.x, w1.x);
                fma2(acc[n][1], a.y, w1.y);
                fma2(acc[n][2], a.x, w2.x);
                fma2(acc[n][2], a.y, w2.y);
                fma2(acc[n][3], a.x, w3.x);
                fma2(acc[n][3], a.y, w3.y);
            }
        }

        // Epilogue: relu + LN (warp-shuffle reduce per node) + affine + mask
#pragma unroll
        for (int n = 0; n < 8; ++n) {
            float h[4];
#pragma unroll
            for (int J = 0; J < 4; ++J) {
                float2 p = unpack2(acc[n][J]);
                h[J] = fmaxf(p.x + p.y + bias[J], 0.f);
            }
            float part = h[0] + h[1] + h[2] + h[3];
#pragma unroll
            for (int o = 16; o > 0; o >>= 1)
                part += __shfl_xor_sync(0xFFFFFFFFu, part, o);
            float mu = part * (1.f / 128.f);
            float d0 = h[0] - mu, d1 = h[1] - mu, d2 = h[2] - mu, d3 = h[3] - mu;
            float p2 = d0 * d0 + d1 * d1 + d2 * d2 + d3 * d3;
#pragma unroll
            for (int o = 16; o > 0; o >>= 1)
                p2 += __shfl_xor_sync(0xFFFFFFFFu, p2, o);
            float rstd = rsqrtf(p2 * (1.f / 128.f) + 1e-5f);

            int gn = node0 + ng * 8 + n;
            float mask = __ldg(&nmask[gn]);
            float* orow = out + (size_t)gn * 128;
            orow[cg +  0] = (d0 * rstd * gm[0] + bt[0]) * mask;
            orow[cg + 32] = (d1 * rstd * gm[1] + bt[1]) * mask;
            orow[cg + 64] = (d2 * rstd * gm[2] + bt[2]) * mask;
            orow[cg + 96] = (d3 * rstd * gm[3] + bt[3]) * mask;
        }
        __syncthreads();
    }
}

// ---------------------------------------------------------------------------
extern "C" void kernel_launch(void* const* d_in, const int* in_sizes, int n_in,
                              void* d_out, int out_size) {
    const float* x     = (const float*)d_in[0];
    const int*   ei    = (const int*)d_in[1];
    const float* nmask = (const float*)d_in[2];
    const float* emask = (const float*)d_in[3];
    const float* Wself = (const float*)d_in[4];
    const float* bself = (const float*)d_in[5];
    const float* Wnb   = (const float*)d_in[6];
    const float* bnb   = (const float*)d_in[7];
    const float* gamma = (const float*)d_in[8];
    const float* beta  = (const float*)d_in[9];
    float* out = (float*)d_out;

    (void)in_sizes; (void)n_in; (void)out_size;

    prep_kernel<<<(NB * DD / 4 + 255) / 256, 256>>>(x);
    hist_kernel<<<(NE / 4 + 255) / 256, 256>>>(ei);
    scan_kernel<<<1, 1024>>>();
    fill_kernel<<<(NE / 4 + 255) / 256, 256>>>(ei, emask);
    gather_kernel<<<(NB * 32 + 255) / 256, 256>>>();

    cudaFuncSetAttribute(fused_kernel, cudaFuncAttributeMaxDynamicSharedMemorySize,
                         FUSED_SMEM_BYTES);
    int nsm = 148;
    cudaDeviceGetAttribute(&nsm, cudaDevAttrMultiProcessorCount, 0);
    fused_kernel<<<nsm, FUSED_THREADS, FUSED_SMEM_BYTES>>>(
        x, Wself, bself, Wnb, bnb, gamma, beta, nmask, out);
}

// round 5
// speedup vs baseline: 1.3606x; 1.3606x over previous
#include <cuda_runtime.h>
#include <cuda_fp16.h>

#define BB 8
#define NN 5000
#define EE 100000
#define DD 128
#define NB (BB * NN)        // 40000
#define NE (BB * EE)        // 800000

typedef unsigned long long u64;
typedef unsigned int u32;

// Scratch (allocation-free: __device__ globals)
__device__ __align__(16) int   g_deg[NB];
__device__ __align__(16) int   g_off[NB];
__device__ __align__(16) int   g_cursor[NB];
__device__ __align__(16) int2  g_bin[NE];
__device__ __align__(16) uint2 g_xh[NB * DD / 4];     // x as 4xhalf chunks
__device__ __align__(16) uint2 g_meanh[NB * DD / 4];  // mean as 4xhalf chunks

// ---------------------------------------------------------------------------
// K0: zero degree counters + convert x -> fp16
// ---------------------------------------------------------------------------
__global__ void prep_kernel(const float* __restrict__ x) {
    int i = blockIdx.x * blockDim.x + threadIdx.x;
    if (i < NB) g_deg[i] = 0;
    if (i < NB * DD / 4) {
        float4 v = __ldg(&((const float4*)x)[i]);
        __half2 h0 = __floats2half2_rn(v.x, v.y);
        __half2 h1 = __floats2half2_rn(v.z, v.w);
        g_xh[i] = make_uint2(*(u32*)&h0, *(u32*)&h1);
    }
}

// ---------------------------------------------------------------------------
// K1: histogram of edge targets (4 edges/thread)
// ---------------------------------------------------------------------------
__global__ void hist_kernel(const int* __restrict__ ei) {
    int t = blockIdx.x * blockDim.x + threadIdx.x;
    int base = t * 4;
    if (base >= NE) return;
    int b = base / EE;
    int e = base - b * EE;
    int4 t4 = __ldg((const int4*)&ei[(size_t)b * 2 * EE + EE + e]);
    int* deg = g_deg + b * NN;
    atomicAdd(&deg[t4.x], 1);
    atomicAdd(&deg[t4.y], 1);
    atomicAdd(&deg[t4.z], 1);
    atomicAdd(&deg[t4.w], 1);
}

// ---------------------------------------------------------------------------
// K2: exclusive prefix sum over 40000 degrees
// ---------------------------------------------------------------------------
__global__ void __launch_bounds__(1024, 1) scan_kernel() {
    __shared__ int part[1024];
    const int t = threadIdx.x;
    const int CH = 40;
    int lo = t * CH;
    if (lo < NB) {
        const int4* d4 = (const int4*)(g_deg + lo);
        int s = 0;
#pragma unroll
        for (int i = 0; i < CH / 4; ++i) {
            int4 v = d4[i];
            s += v.x + v.y + v.z + v.w;
        }
        part[t] = s;
    } else {
        part[t] = 0;
    }
    __syncthreads();

    for (int o = 1; o < 1024; o <<= 1) {
        int v = (t >= o) ? part[t - o] : 0;
        __syncthreads();
        part[t] += v;
        __syncthreads();
    }

    if (lo < NB) {
        int run = (t > 0) ? part[t - 1] : 0;
        const int4* d4 = (const int4*)(g_deg + lo);
        int4* o4 = (int4*)(g_off + lo);
        int4* c4 = (int4*)(g_cursor + lo);
#pragma unroll
        for (int i = 0; i < CH / 4; ++i) {
            int4 v = d4[i];
            int4 w;
            w.x = run; run += v.x;
            w.y = run; run += v.y;
            w.z = run; run += v.z;
            w.w = run; run += v.w;
            o4[i] = w;
            c4[i] = w;
        }
    }
}

// ---------------------------------------------------------------------------
// K3: fill bins (4 edges/thread, independent atomic chains)
// ---------------------------------------------------------------------------
__global__ void fill_kernel(const int* __restrict__ ei,
                            const float* __restrict__ em) {
    int t = blockIdx.x * blockDim.x + threadIdx.x;
    int base = t * 4;
    if (base >= NE) return;
    int b = base / EE;
    int e = base - b * EE;
    const int* eb = ei + (size_t)b * 2 * EE;
    int4 s4 = __ldg((const int4*)&eb[e]);
    int4 t4 = __ldg((const int4*)&eb[EE + e]);
    float4 m4 = __ldg((const float4*)&em[(size_t)b * EE + e]);
    int* cur = g_cursor + b * NN;
    int p0 = atomicAdd(&cur[t4.x], 1);
    int p1 = atomicAdd(&cur[t4.y], 1);
    int p2 = atomicAdd(&cur[t4.z], 1);
    int p3 = atomicAdd(&cur[t4.w], 1);
    g_bin[p0] = make_int2(s4.x, __float_as_int(m4.x));
    g_bin[p1] = make_int2(s4.y, __float_as_int(m4.y));
    g_bin[p2] = make_int2(s4.z, __float_as_int(m4.z));
    g_bin[p3] = make_int2(s4.w, __float_as_int(m4.w));
}

// ---------------------------------------------------------------------------
// K4: gather (fp16 rows in, fp32 accum, fp16 mean out)
// ---------------------------------------------------------------------------
__global__ void gather_kernel() {
    int g = (blockIdx.x * blockDim.x + threadIdx.x) >> 5;
    int lane = threadIdx.x & 31;
    if (g >= NB) return;
    int b = g / NN;

    const int deg = g_deg[g];
    const int off = g_off[g];
    const uint2* xr = g_xh + (size_t)b * NN * 32;

    float4 acc = make_float4(0.f, 0.f, 0.f, 0.f);
    float cm = 0.f;

#define EDGE_FMA(u, m)                                                        \
    {                                                                         \
        float2 a = __half22float2(*(__half2*)&(u).x);                         \
        float2 c = __half22float2(*(__half2*)&(u).y);                         \
        acc.x = fmaf(a.x, (m), acc.x);                                        \
        acc.y = fmaf(a.y, (m), acc.y);                                        \
        acc.z = fmaf(c.x, (m), acc.z);                                        \
        acc.w = fmaf(c.y, (m), acc.w);                                        \
        cm += (m);                                                            \
    }

    int j = 0;
    for (; j + 4 <= deg; j += 4) {
        int2 r0 = __ldg(&g_bin[off + j]);
        int2 r1 = __ldg(&g_bin[off + j + 1]);
        int2 r2 = __ldg(&g_bin[off + j + 2]);
        int2 r3 = __ldg(&g_bin[off + j + 3]);
        uint2 u0 = __ldg(&xr[(size_t)r0.x * 32 + lane]);
        uint2 u1 = __ldg(&xr[(size_t)r1.x * 32 + lane]);
        uint2 u2 = __ldg(&xr[(size_t)r2.x * 32 + lane]);
        uint2 u3 = __ldg(&xr[(size_t)r3.x * 32 + lane]);
        EDGE_FMA(u0, __int_as_float(r0.y))
        EDGE_FMA(u1, __int_as_float(r1.y))
        EDGE_FMA(u2, __int_as_float(r2.y))
        EDGE_FMA(u3, __int_as_float(r3.y))
    }
    for (; j < deg; ++j) {
        int2 r = __ldg(&g_bin[off + j]);
        uint2 u = __ldg(&xr[(size_t)r.x * 32 + lane]);
        EDGE_FMA(u, __int_as_float(r.y))
    }
#undef EDGE_FMA

    float inv = 1.f / fmaxf(cm, 1.f);
    __half2 h0 = __floats2half2_rn(acc.x * inv, acc.y * inv);
    __half2 h1 = __floats2half2_rn(acc.z * inv, acc.w * inv);
    g_meanh[(size_t)g * 32 + lane] = make_uint2(*(u32*)&h0, *(u32*)&h1);
}

// ---------------------------------------------------------------------------
// K5: fused HMMA GEMM + relu + LN + mask.
// A = [x || mean] fp16 (k=256), B = [Wself ; Wnb] fp16 (k=256, n=128).
// Block: 256 threads = 8 warps. Warp owns 16 nodes x 128 cols
// (16 n-tiles of m16n8k16). Tile = 128 nodes. fp32 accum, bias folded in.
// smem pitches: inSh 264 halfs (528B), Wh 136 halfs (272B) -> ldmatrix
// phases hit distinct 16B granules (stride mod 128B = 16).
// ---------------------------------------------------------------------------
#define FUSED_THREADS 256
#define IN_PITCH 264                          // halfs per inSh row
#define W_PITCH_H 136                         // halfs per Wh row
#define SMEM_WH_BYTES (256 * W_PITCH_H * 2)   // 69632
#define SMEM_IN_BYTES (128 * IN_PITCH * 2)    // 67584
#define SMEM_CONST_BYTES (3 * 128 * 4)        // 1536
#define FUSED_SMEM_BYTES (SMEM_WH_BYTES + SMEM_IN_BYTES + SMEM_CONST_BYTES)
#define NTILES ((NB + 127) / 128)             // 313

__device__ __forceinline__ u32 smem_u32(const void* p) {
    u32 a;
    asm("{ .reg .u64 t; cvta.to.shared.u64 t, %1; cvt.u32.u64 %0, t; }"
        : "=r"(a) : "l"(p));
    return a;
}
__device__ __forceinline__ void ldsm_x4(u32& r0, u32& r1, u32& r2, u32& r3, u32 a) {
    asm volatile("ldmatrix.sync.aligned.m8n8.x4.shared.b16 {%0,%1,%2,%3}, [%4];"
                 : "=r"(r0), "=r"(r1), "=r"(r2), "=r"(r3) : "r"(a));
}
__device__ __forceinline__ void ldsm_x4t(u32& r0, u32& r1, u32& r2, u32& r3, u32 a) {
    asm volatile("ldmatrix.sync.aligned.m8n8.x4.trans.shared.b16 {%0,%1,%2,%3}, [%4];"
                 : "=r"(r0), "=r"(r1), "=r"(r2), "=r"(r3) : "r"(a));
}
__device__ __forceinline__ void mma16816(float* c, u32 a0, u32 a1, u32 a2, u32 a3,
                                         u32 b0, u32 b1) {
    asm volatile(
        "mma.sync.aligned.m16n8k16.row.col.f32.f16.f16.f32 "
        "{%0,%1,%2,%3}, {%4,%5,%6,%7}, {%8,%9}, {%0,%1,%2,%3};"
        : "+f"(c[0]), "+f"(c[1]), "+f"(c[2]), "+f"(c[3])
        : "r"(a0), "r"(a1), "r"(a2), "r"(a3), "r"(b0), "r"(b1));
}

__global__ void __launch_bounds__(FUSED_THREADS, 1)
fused_kernel(const float* __restrict__ Wself,
             const float* __restrict__ bself,
             const float* __restrict__ Wnb,
             const float* __restrict__ bnb,
             const float* __restrict__ gamma,
             const float* __restrict__ beta,
             const float* __restrict__ nmask,
             float* __restrict__ out) {
    extern __shared__ char sm[];
    __half* Wh = (__half*)sm;                          // [256][136]
    __half* inSh = (__half*)(sm + SMEM_WH_BYTES);      // [128][264]
    float* bias_sm = (float*)(sm + SMEM_WH_BYTES + SMEM_IN_BYTES);
    float* gm_sm = bias_sm + 128;
    float* bt_sm = gm_sm + 128;

    const int tid = threadIdx.x;
    const int lane = tid & 31;
    const int wid = tid >> 5;

    // Weights -> fp16 smem (once per block)
    for (int i = tid; i < 256 * 128; i += FUSED_THREADS) {
        int k = i >> 7;
        int n = i & 127;
        float w = (k < 128) ? __ldg(&Wself[k * 128 + n])
                            : __ldg(&Wnb[(k - 128) * 128 + n]);
        Wh[k * W_PITCH_H + n] = __float2half_rn(w);
    }
    if (tid < 128) {
        bias_sm[tid] = __ldg(&bself[tid]) + __ldg(&bnb[tid]);
        gm_sm[tid] = __ldg(&gamma[tid]);
        bt_sm[tid] = __ldg(&beta[tid]);
    }
    __syncthreads();

    const u32 in_u = smem_u32(inSh);
    const u32 wh_u = smem_u32(Wh);
    // Per-lane ldmatrix address components
    const u32 a_row_off = (u32)(wid * 16 + (lane & 15)) * (IN_PITCH * 2)
                        + (u32)((lane >> 4) * 8) * 2;       // + ks*32B
    const u32 b_row_lane = (u32)(lane & 15) * (W_PITCH_H * 2);
    const u32 b_col_lane = (u32)((lane >> 4) * 8) * 2;

    for (int tile = blockIdx.x; tile < NTILES; tile += gridDim.x) {
        const int node0 = tile * 128;

        // Fill inSh: k<128 from x(fp16), k>=128 from mean(fp16); zero pad rows
        for (int i = tid; i < 128 * 64; i += FUSED_THREADS) {
            int nl = i >> 6;
            int c = i & 63;
            int gn = node0 + nl;
            uint2 v = make_uint2(0u, 0u);
            if (gn < NB)
                v = (c < 32) ? __ldg(&g_xh[(size_t)gn * 32 + c])
                             : __ldg(&g_meanh[(size_t)gn * 32 + (c - 32)]);
            *(uint2*)((char*)inSh + (size_t)nl * (IN_PITCH * 2) + (size_t)c * 8) = v;
        }
        __syncthreads();

        // Accumulators: 16 n-tiles x 4 floats, init with bias
        float acc[16][4];
#pragma unroll
        for (int j = 0; j < 16; ++j) {
            float2 bv = *(float2*)&bias_sm[j * 8 + (lane & 3) * 2];
            acc[j][0] = bv.x; acc[j][1] = bv.y;
            acc[j][2] = bv.x; acc[j][3] = bv.y;
        }

#pragma unroll 1
        for (int ks = 0; ks < 16; ++ks) {
            u32 a0, a1, a2, a3;
            ldsm_x4(a0, a1, a2, a3, in_u + a_row_off + (u32)ks * 32);
            u32 brow = wh_u + (u32)ks * 16 * (W_PITCH_H * 2) + b_row_lane + b_col_lane;
#pragma unroll
            for (int jt = 0; jt < 8; ++jt) {
                u32 b0, b1, b2, b3;
                ldsm_x4t(b0, b1, b2, b3, brow + (u32)jt * 32);
                mma16816(acc[2 * jt], a0, a1, a2, a3, b0, b1);
                mma16816(acc[2 * jt + 1], a0, a1, a2, a3, b2, b3);
            }
        }

        // Epilogue: relu + LN (rows r0, r1 per lane; 4-lane shuffle reduce)
#pragma unroll
        for (int j = 0; j < 16; ++j) {
            acc[j][0] = fmaxf(acc[j][0], 0.f);
            acc[j][1] = fmaxf(acc[j][1], 0.f);
            acc[j][2] = fmaxf(acc[j][2], 0.f);
            acc[j][3] = fmaxf(acc[j][3], 0.f);
        }
        float s0 = 0.f, s1 = 0.f;
#pragma unroll
        for (int j = 0; j < 16; ++j) {
            s0 += acc[j][0] + acc[j][1];
            s1 += acc[j][2] + acc[j][3];
        }
        s0 += __shfl_xor_sync(0xFFFFFFFFu, s0, 1);
        s0 += __shfl_xor_sync(0xFFFFFFFFu, s0, 2);
        s1 += __shfl_xor_sync(0xFFFFFFFFu, s1, 1);
        s1 += __shfl_xor_sync(0xFFFFFFFFu, s1, 2);
        float mu0 = s0 * (1.f / 128.f);
        float mu1 = s1 * (1.f / 128.f);

        float v0 = 0.f, v1 = 0.f;
#pragma unroll
        for (int j = 0; j < 16; ++j) {
            float d0 = acc[j][0] - mu0, d1 = acc[j][1] - mu0;
            float d2 = acc[j][2] - mu1, d3 = acc[j][3] - mu1;
            v0 += d0 * d0 + d1 * d1;
            v1 += d2 * d2 + d3 * d3;
        }
        v0 += __shfl_xor_sync(0xFFFFFFFFu, v0, 1);
        v0 += __shfl_xor_sync(0xFFFFFFFFu, v0, 2);
        v1 += __shfl_xor_sync(0xFFFFFFFFu, v1, 1);
        v1 += __shfl_xor_sync(0xFFFFFFFFu, v1, 2);
        float rstd0 = rsqrtf(v0 * (1.f / 128.f) + 1e-5f);
        float rstd1 = rsqrtf(v1 * (1.f / 128.f) + 1e-5f);

        int r0 = node0 + wid * 16 + (lane >> 2);
        int r1 = r0 + 8;
        float mk0 = (r0 < NB) ? __ldg(&nmask[r0]) : 0.f;
        float mk1 = (r1 < NB) ? __ldg(&nmask[r1]) : 0.f;
        float a0s = rstd0 * mk0, a1s = rstd1 * mk1;

#pragma unroll
        for (int j = 0; j < 16; ++j) {
            int col = j * 8 + (lane & 3) * 2;
            float2 g2 = *(float2*)&gm_sm[col];
            float2 b2 = *(float2*)&bt_sm[col];
            if (r0 < NB) {
                float2 o;
                o.x = ((acc[j][0] - mu0) * g2.x * a0s) + b2.x * mk0;
                o.y = ((acc[j][1] - mu0) * g2.y * a0s) + b2.y * mk0;
                *(float2*)&out[(size_t)r0 * 128 + col] = o;
            }
            if (r1 < NB) {
                float2 o;
                o.x = ((acc[j][2] - mu1) * g2.x * a1s) + b2.x * mk1;
                o.y = ((acc[j][3] - mu1) * g2.y * a1s) + b2.y * mk1;
                *(float2*)&out[(size_t)r1 * 128 + col] = o;
            }
        }
        __syncthreads();
    }
}

// ---------------------------------------------------------------------------
extern "C" void kernel_launch(void* const* d_in, const int* in_sizes, int n_in,
                              void* d_out, int out_size) {
    const float* x     = (const float*)d_in[0];
    const int*   ei    = (const int*)d_in[1];
    const float* nmask = (const float*)d_in[2];
    const float* emask = (const float*)d_in[3];
    const float* Wself = (const float*)d_in[4];
    const float* bself = (const float*)d_in[5];
    const float* Wnb   = (const float*)d_in[6];
    const float* bnb   = (const float*)d_in[7];
    const float* gamma = (const float*)d_in[8];
    const float* beta  = (const float*)d_in[9];
    float* out = (float*)d_out;

    (void)in_sizes; (void)n_in; (void)out_size;

    prep_kernel<<<(NB * DD / 4 + 255) / 256, 256>>>(x);
    hist_kernel<<<(NE / 4 + 255) / 256, 256>>>(ei);
    scan_kernel<<<1, 1024>>>();
    fill_kernel<<<(NE / 4 + 255) / 256, 256>>>(ei, emask);
    gather_kernel<<<(NB * 32 + 255) / 256, 256>>>();

    cudaFuncSetAttribute(fused_kernel, cudaFuncAttributeMaxDynamicSharedMemorySize,
                         FUSED_SMEM_BYTES);
    int nsm = 148;
    cudaDeviceGetAttribute(&nsm, cudaDevAttrMultiProcessorCount, 0);
    fused_kernel<<<nsm, FUSED_THREADS, FUSED_SMEM_BYTES>>>(
        Wself, bself, Wnb, bnb, gamma, beta, nmask, out);
}